// round 9
// baseline (speedup 1.0000x reference)
#include <cuda_runtime.h>
#include <math.h>
#include <stdint.h>

#define BATCH 16
#define KBOX  128
#define NUMC  80
#define OH    128
#define OW    128
#define NB    (BATCH*KBOX)
#define PLANE (OH*OW)
#define NBLK  (BATCH*NUMC*2)          // 2560 blocks: (b, c, half)

// ---- per-box scratch (sorted order) ----
__device__ float d_bx1[NB], d_by1[NB], d_bx2[NB], d_by2[NB];
__device__ float d_i2sy[NB], d_i2sx[NB], d_coef[NB];
__device__ int   d_cls[NB], d_cx[NB], d_cy[NB], d_hr[NB], d_wr[NB], d_act[NB];

// ---- per-block partial slots + ticket (self-resetting) ----
__device__ float d_part_hm[NBLK], d_part_whn[NBLK], d_part_rw[NBLK];
__device__ int   d_part_np[NBLK];
__device__ unsigned int d_done_ctr;

// u(x) = log(1 - clip(sigmoid(x))) * clip(sigmoid(x))^2
__device__ __forceinline__ float focal_neg_base(float xv, float& p_out) {
    float t = __expf(-xv);
    float p = __fdividef(1.0f, 1.0f + t);
    p = fminf(fmaxf(p, 1e-4f), 0.9999f);
    p_out = p;
    float omp = 1.0f - p;
    return __logf(omp) * p * p;
}

// =====================================================================
// prep: mask decode + per-image sort + per-box params. grid=(16), 128thr
// =====================================================================
__global__ void prep_kernel(const float* __restrict__ tgt,
                            const void* __restrict__ mraw) {
    int b = blockIdx.x;
    int k = threadIdx.x;
    __shared__ float skey[KBOX];
    __shared__ int   sperm[KBOX];
    __shared__ int   smask[KBOX];
    __shared__ float s_al0;
    __shared__ int   s_gt1, s_off4;

    if (k == 0) { s_gt1 = 0; s_off4 = 0; }
    __syncthreads();
    {
        const uint8_t* b8 = (const uint8_t*)mraw;
        int gt1 = 0, off4 = 0;
#pragma unroll
        for (int c = 0; c < NB/KBOX; c++) {
            int i = c*KBOX + k;
            uint8_t v = b8[i];
            gt1  |= (v > 1);
            off4 |= (v != 0) && ((i & 3) != 0);
        }
        if (gt1)  atomicOr(&s_gt1, 1);
        if (off4) atomicOr(&s_off4, 1);
    }
    __syncthreads();
    int u8mode = (!s_gt1) && s_off4;
    {
        int i = b*KBOX + k;
        smask[k] = u8mode ? (((const uint8_t*)mraw)[i] != 0)
                          : (((const uint32_t*)mraw)[i] != 0u);
    }
    __syncthreads();

    const float* t = tgt + (size_t)(b*KBOX + k)*5;
    float x1 = t[1], y1 = t[2], x2 = t[3], y2 = t[4];
    float area = (x2 - x1) * (y2 - y1);
    float key = smask[k] ? __logf(area) : -INFINITY;
    skey[k] = key;
    __syncthreads();

    int rank = 0;
#pragma unroll 16
    for (int j = 0; j < KBOX; j++) {
        float kj = skey[j];
        rank += (kj > key) || (kj == key && j < k);
    }
    sperm[rank] = k;
    __syncthreads();

    if (k == 0) {
        int o0 = sperm[0];
        s_al0 = smask[o0] ? skey[o0] : 0.0f;
    }
    __syncthreads();

    int o = sperm[k];
    const float* to = tgt + (size_t)(b*KBOX + o)*5;
    float clsf = to[0];
    float ox1 = to[1], oy1 = to[2], ox2 = to[3], oy2 = to[4];
    int v = smask[o];
    float keyo = skey[o];

    float fx1 = fminf(fmaxf(ox1 * 0.25f, 0.0f), (float)(OW-1));
    float fy1 = fminf(fmaxf(oy1 * 0.25f, 0.0f), (float)(OH-1));
    float fx2 = fminf(fmaxf(ox2 * 0.25f, 0.0f), (float)(OW-1));
    float fy2 = fminf(fmaxf(oy2 * 0.25f, 0.0f), (float)(OH-1));
    float feat_h = fy2 - fy1;
    float feat_w = fx2 - fx1;

    int cx = (int)(((ox1 + ox2) * 0.5f) * 0.25f);
    int cy = (int)(((oy1 + oy2) * 0.5f) * 0.25f);
    int hr = (int)((feat_h * 0.5f) * 0.54f);
    int wr = (int)((feat_w * 0.5f) * 0.54f);
    float sy = (float)(2*hr + 1) / 6.0f;
    float sx = (float)(2*wr + 1) / 6.0f;
    float i2sy = 1.0f / (2.0f * sy * sy);
    float i2sx = 1.0f / (2.0f * sx * sx);

    int act = v && (cx >= 0) && (cx < OW) && (cy >= 0) && (cy < OH);

    float divs = 0.0f;
    if (act) {
        float sgy = 0.0f, sgx = 0.0f;
        int ya = max(0, cy - hr), yb = min(OH-1, cy + hr);
        for (int yy = ya; yy <= yb; yy++) {
            float d = (float)(yy - cy);
            sgy += __expf(-(d*d) * i2sy);
        }
        int xa = max(0, cx - wr), xb = min(OW-1, cx + wr);
        for (int xx = xa; xx <= xb; xx++) {
            float d = (float)(xx - cx);
            sgx += __expf(-(d*d) * i2sx);
        }
        divs = sgy * sgx;
    }
    float al = v ? keyo : 0.0f;
    float factor = 2.0f - al / (s_al0 + 1e-7f);
    float coef = act ? (factor / (divs + 1e-7f)) : 0.0f;

    int idx = b*KBOX + k;
    d_bx1[idx] = ox1; d_by1[idx] = oy1; d_bx2[idx] = ox2; d_by2[idx] = oy2;
    d_i2sy[idx] = i2sy; d_i2sx[idx] = i2sx; d_coef[idx] = coef;
    d_cls[idx] = (int)clsf; d_cx[idx] = cx; d_cy[idx] = cy;
    d_hr[idx] = hr; d_wr[idx] = wr; d_act[idx] = act;
}

// =====================================================================
// mega: per block = (b, c, half). Streams 64 rows of one class plane,
// applies class-c corrections for those rows; c==0 blocks also do the
// classless winner/IoU for their 64 rows. Last block finalizes.
// =====================================================================
__global__ void __launch_bounds__(256)
mega_kernel(const float* __restrict__ hm,
            const float* __restrict__ wh,
            float* __restrict__ out) {
    int bid = blockIdx.x;
    int tid = threadIdx.x;
    int lane = tid & 31;
    int wrp  = tid >> 5;

    int b    = bid / (NUMC*2);
    int rem  = bid % (NUMC*2);
    int c    = rem >> 1;
    int half = rem & 1;
    int r0   = half * 64;
    int r1   = r0 + 63;

    float lsum = 0.0f, lwhn = 0.0f, lrw = 0.0f;
    int   lnp  = 0;

    // ---------------- base: stream 2048 float4 ----------------
    {
        const float4* hm4 = (const float4*)hm;
        int idx = bid * 2048 + tid;
        float4 v[8];
#pragma unroll
        for (int u = 0; u < 8; u++) v[u] = __ldg(&hm4[idx + u*256]);
#pragma unroll
        for (int u = 0; u < 8; u++) {
            float p;
            lsum += focal_neg_base(v[u].x, p);
            lsum += focal_neg_base(v[u].y, p);
            lsum += focal_neg_base(v[u].z, p);
            lsum += focal_neg_base(v[u].w, p);
        }
    }

    // ---------------- box filtering ----------------
    __shared__ uint8_t fC[KBOX], fA[KBOX];
    __shared__ short   clist[KBOX];
    __shared__ int     s_cn, s_an;
    // class-c list data
    __shared__ float ci2x[KBOX], ci2y[KBOX];
    __shared__ short ccx[KBOX], ccy[KBOX], chr_[KBOX], cwr[KBOX];
    // any-class list data (only used by c==0 blocks)
    __shared__ float ax1[KBOX], ay1[KBOX], ax2[KBOX], ay2[KBOX];
    __shared__ float acoef[KBOX], ai2x[KBOX], ai2y[KBOX];
    __shared__ short acx[KBOX], acy[KBOX], ahr[KBOX], awr[KBOX];

    if (tid < KBOX) {
        int base = b*KBOX + tid;
        int act = d_act[base];
        int cy = d_cy[base], hr = d_hr[base];
        int inter = act && (cy + hr >= r0) && (cy - hr <= r1);
        fA[tid] = (uint8_t)inter;
        fC[tid] = (uint8_t)(inter && (d_cls[base] == c));
    }
    __syncthreads();
    if (tid == 0) {
        int nn = 0;
        for (int j = 0; j < KBOX; j++)
            if (fC[j]) clist[nn++] = (short)j;
        s_cn = nn;
    } else if (tid == 32 && c == 0) {
        // any-class compaction into tail of smem via fA -> reuse clist? no:
        // store ascending indices in a second pass below (serial here).
        int nn = 0;
        for (int j = 0; j < KBOX; j++)
            if (fA[j]) { ax1[nn] = (float)j; nn++; }   // temp: index in ax1
        s_an = nn;
    }
    __syncthreads();
    int cn = s_cn;
    int an = (c == 0) ? s_an : 0;

    if (tid < cn) {
        int j = clist[tid];
        int base = b*KBOX + j;
        ci2x[tid] = d_i2sx[base]; ci2y[tid] = d_i2sy[base];
        ccx[tid] = (short)d_cx[base]; ccy[tid] = (short)d_cy[base];
        chr_[tid] = (short)d_hr[base]; cwr[tid] = (short)d_wr[base];
    }
    if (c == 0 && tid >= 128 && (tid - 128) < an) {
        int e = tid - 128;
        int j = (int)ax1[e];
        int base = b*KBOX + j;
        ai2x[e] = d_i2sx[base]; ai2y[e] = d_i2sy[base];
        acoef[e] = d_coef[base];
        acx[e] = (short)d_cx[base]; acy[e] = (short)d_cy[base];
        ahr[e] = (short)d_hr[base]; awr[e] = (short)d_wr[base];
        ay1[e] = d_by1[base]; ay2[e] = d_by2[base];
        ax2[e] = d_bx2[base];
    }
    __syncthreads();
    // ax1 was used as temp for indices; rewrite with real x1 now
    if (c == 0 && tid < an) {
        int j = (int)ax1[tid];
        ax1[tid] = d_bx1[b*KBOX + j];
    }
    __syncthreads();

    // ---------------- class-c corrections ----------------
    const float* hmplane = hm + ((size_t)(b*NUMC + c)) * PLANE;
    for (int e = 0; e < cn; e++) {
        int cx = ccx[e], cy = ccy[e], hr = chr_[e], wr = cwr[e];
        float i2x = ci2x[e], i2y = ci2y[e];
        int ya = max(cy - hr, r0), yb = min(cy + hr, r1);
        int xa = max(cx - wr, 0),  xb = min(cx + wr, OW-1);
        int W = xb - xa + 1;
        int npix = (yb - ya + 1) * W;
        for (int pi = tid; pi < npix; pi += 256) {
            int y = ya + pi / W;
            int x = xa + pi % W;
            float dyf = (float)(y - cy);
            float dxf = (float)(x - cx);
            float g = __expf(-dyf*dyf * i2y) * __expf(-dxf*dxf * i2x);
            bool rep = true;
            for (int e2 = 0; e2 < cn; e2++) {
                if (e2 == e) continue;
                int dy2 = y - ccy[e2];
                int dx2 = x - ccx[e2];
                if (abs(dy2) > chr_[e2] || abs(dx2) > cwr[e2]) continue;
                float fy2 = (float)dy2, fx2 = (float)dx2;
                float g2 = __expf(-fy2*fy2 * ci2y[e2]) * __expf(-fx2*fx2 * ci2x[e2]);
                if (g2 > g || (g2 == g && e2 < e)) { rep = false; break; }
            }
            if (!rep) continue;
            float xv = hmplane[y*OW + x];
            float p;
            float u = focal_neg_base(xv, p);
            if (g == 1.0f) {
                float omp = 1.0f - p;
                lsum += __logf(p) * omp * omp - u;
                lnp++;
            } else {
                float omh = 1.0f - g;
                float w4 = omh * omh; w4 *= w4;
                lsum += u * (w4 - 1.0f);
            }
        }
    }

    // ---------------- winner/IoU (c==0 blocks, 64 rows) ----------------
    if (c == 0) {
        // warp wrp handles rows r0 + wrp*8 .. +7 ; lane handles 4 px
        int xg = lane * 4;
        for (int rr = 0; rr < 8; rr++) {
            int y = r0 + wrp*8 + rr;
            int win0 = -1, win1 = -1, win2 = -1, win3 = -1;
            for (int e = 0; e < an; e++) {
                int dy = y - acy[e];
                if (abs(dy) > ahr[e]) continue;
                int cx = acx[e], wr = awr[e];
                if (abs(xg     - cx) <= wr) win0 = e;
                if (abs(xg + 1 - cx) <= wr) win1 = e;
                if (abs(xg + 2 - cx) <= wr) win2 = e;
                if (abs(xg + 3 - cx) <= wr) win3 = e;
            }
            if ((win0 | win1 | win2 | win3) != -1 || win0 >= 0 || win1 >= 0 || win2 >= 0 || win3 >= 0) {
                size_t wb = (((size_t)b*4)*OH + y)*OW + xg;
                float4 p0 = *(const float4*)(wh + wb);
                float4 p1 = *(const float4*)(wh + wb +   PLANE);
                float4 p2 = *(const float4*)(wh + wb + 2*PLANE);
                float4 p3 = *(const float4*)(wh + wb + 3*PLANE);
                int wins[4] = {win0, win1, win2, win3};
                float ys = (float)y * 4.0f;
#pragma unroll
                for (int i = 0; i < 4; i++) {
                    int e = wins[i];
                    if (e < 0) continue;
                    int x = xg + i;
                    float dyf = (float)(y - acy[e]);
                    float dxf = (float)(x - acx[e]);
                    float g = __expf(-dyf*dyf * ai2y[e]) * __expf(-dxf*dxf * ai2x[e]);
                    float rw = g * acoef[e];
                    float pl = (&p0.x)[i] * 16.0f;
                    float pt = (&p1.x)[i] * 16.0f;
                    float pr = (&p2.x)[i] * 16.0f;
                    float pb = (&p3.x)[i] * 16.0f;
                    float xs = (float)x * 4.0f;
                    float tl = xs - ax1[e];
                    float tt = ys - ay1[e];
                    float tr = ax2[e] - xs;
                    float tb = ay2[e] - ys;
                    float ta = (tl + tr) * (tt + tb);
                    float pa = (pl + pr) * (pt + pb);
                    float wi = fminf(pl, tl) + fminf(pr, tr);
                    float hi = fminf(pt, tt) + fminf(pb, tb);
                    float ai = wi * hi;
                    float au = ta + pa - ai;
                    float iou = (ai + 1.0f) / (au + 1.0f);
                    lwhn += (rw > 0.0f) ? (1.0f - iou) * rw : 0.0f;
                    lrw  += rw;
                }
            }
        }
    }

    // ---------------- block reduce -> slot; last block finalizes ----------------
    for (int off = 16; off; off >>= 1) {
        lsum += __shfl_down_sync(0xffffffffu, lsum, off);
        lwhn += __shfl_down_sync(0xffffffffu, lwhn, off);
        lrw  += __shfl_down_sync(0xffffffffu, lrw,  off);
        lnp  += __shfl_down_sync(0xffffffffu, lnp,  off);
    }
    __shared__ float r0s[8], r1s[8], r2s[8];
    __shared__ int   r3s[8];
    if (lane == 0) { r0s[wrp]=lsum; r1s[wrp]=lwhn; r2s[wrp]=lrw; r3s[wrp]=lnp; }
    __syncthreads();
    if (tid == 0) {
        float a=0.f, c1=0.f, c2=0.f; int np=0;
#pragma unroll
        for (int i = 0; i < 8; i++) { a+=r0s[i]; c1+=r1s[i]; c2+=r2s[i]; np+=r3s[i]; }
        d_part_hm[bid]  = a;
        d_part_whn[bid] = c1;
        d_part_rw[bid]  = c2;
        d_part_np[bid]  = np;
    }
    __shared__ bool amLast;
    __threadfence();
    __syncthreads();
    if (tid == 0)
        amLast = (atomicAdd(&d_done_ctr, 1u) == (unsigned)(NBLK - 1));
    __syncthreads();
    if (amLast) {
        double shm = 0.0, swn = 0.0, srw = 0.0;
        int snp = 0;
        for (int i = tid; i < NBLK; i += 256) {
            shm += (double)d_part_hm[i];
            swn += (double)d_part_whn[i];
            srw += (double)d_part_rw[i];
            snp += d_part_np[i];
        }
        for (int off = 16; off; off >>= 1) {
            shm += __shfl_down_sync(0xffffffffu, shm, off);
            swn += __shfl_down_sync(0xffffffffu, swn, off);
            srw += __shfl_down_sync(0xffffffffu, srw, off);
            snp += __shfl_down_sync(0xffffffffu, snp, off);
        }
        __shared__ double q0[8], q1[8], q2[8];
        __shared__ int    q3[8];
        if (lane == 0) { q0[wrp]=shm; q1[wrp]=swn; q2[wrp]=srw; q3[wrp]=snp; }
        __syncthreads();
        if (tid == 0) {
            double thm=0.0, twn=0.0, trw=0.0; int tnp=0;
#pragma unroll
            for (int i = 0; i < 8; i++) { thm+=q0[i]; twn+=q1[i]; trw+=q2[i]; tnp+=q3[i]; }
            double hml = (tnp > 0) ? (-thm / (double)(tnp < 1 ? 1 : tnp)) : -thm;
            double whl = twn / fmax(trw, 1.0);
            out[0] = (float)(hml + whl);
            d_done_ctr = 0u;
        }
    }
}

extern "C" void kernel_launch(void* const* d_in, const int* in_sizes, int n_in,
                              void* d_out, int out_size) {
    const float* hm   = (const float*)d_in[0];
    const float* wh   = (const float*)d_in[1];
    const float* tgt  = (const float*)d_in[2];
    const void*  mask = (const void*)d_in[3];
    float* out = (float*)d_out;
    (void)in_sizes; (void)n_in; (void)out_size;

    prep_kernel<<<BATCH, KBOX>>>(tgt, mask);
    mega_kernel<<<NBLK, 256>>>(hm, wh, out);
}

// round 12
// speedup vs baseline: 1.1269x; 1.1269x over previous
#include <cuda_runtime.h>
#include <math.h>
#include <stdint.h>

#define BATCH 16
#define KBOX  128
#define NUMC  80
#define OH    128
#define OW    128
#define NB    (BATCH*KBOX)
#define PLANE (OH*OW)
#define NBASE 2560                 // (16*80*128*128/4) / (256*8)
#define NSPA  1024                 // 2 rows per block
#define NTOT  (NBASE + NSPA)       // 3584

// ---- per-block partial slots + ticket (self-resetting) ----
__device__ float d_part_hm[NTOT], d_part_whn[NTOT], d_part_rw[NTOT];
__device__ int   d_part_np[NTOT];
__device__ unsigned int d_done_ctr;

// u(x) = log(1 - clip(sigmoid(x))) * clip(sigmoid(x))^2   (3 MUFU)
__device__ __forceinline__ float focal_neg_base(float xv, float& p_out) {
    float t = __expf(-xv);
    float p = __fdividef(1.0f, 1.0f + t);
    p = fminf(fmaxf(p, 1e-4f), 0.9999f);
    p_out = p;
    float omp = 1.0f - p;
    return __logf(omp) * p * p;
}

// block(256thr) reduce -> slot; globally-last block finalizes + resets.
__device__ __forceinline__ void commit_and_maybe_finalize(
        int slot, float lsum, float lwhn, float lrw, int lnp, float* out) {
    int tid = threadIdx.x, lane = tid & 31, wrp = tid >> 5;
    for (int off = 16; off; off >>= 1) {
        lsum += __shfl_down_sync(0xffffffffu, lsum, off);
        lwhn += __shfl_down_sync(0xffffffffu, lwhn, off);
        lrw  += __shfl_down_sync(0xffffffffu, lrw,  off);
        lnp  += __shfl_down_sync(0xffffffffu, lnp,  off);
    }
    __shared__ float r0[8], r1[8], r2[8];
    __shared__ int   r3[8];
    if (lane == 0) { r0[wrp]=lsum; r1[wrp]=lwhn; r2[wrp]=lrw; r3[wrp]=lnp; }
    __syncthreads();
    if (tid == 0) {
        float a=0.f, c1=0.f, c2=0.f; int np=0;
#pragma unroll
        for (int i = 0; i < 8; i++) { a+=r0[i]; c1+=r1[i]; c2+=r2[i]; np+=r3[i]; }
        d_part_hm[slot]  = a;
        d_part_whn[slot] = c1;
        d_part_rw[slot]  = c2;
        d_part_np[slot]  = np;
    }
    __shared__ bool amLast;
    __threadfence();
    __syncthreads();
    if (tid == 0)
        amLast = (atomicAdd(&d_done_ctr, 1u) == (unsigned)(NTOT - 1));
    __syncthreads();
    if (amLast) {
        double shm = 0.0, swn = 0.0, srw = 0.0;
        int snp = 0;
        for (int i = tid; i < NTOT; i += 256) {
            shm += (double)d_part_hm[i];
            swn += (double)d_part_whn[i];
            srw += (double)d_part_rw[i];
            snp += d_part_np[i];
        }
        for (int off = 16; off; off >>= 1) {
            shm += __shfl_down_sync(0xffffffffu, shm, off);
            swn += __shfl_down_sync(0xffffffffu, swn, off);
            srw += __shfl_down_sync(0xffffffffu, srw, off);
            snp += __shfl_down_sync(0xffffffffu, snp, off);
        }
        __shared__ double q0[8], q1[8], q2[8];
        __shared__ int    q3[8];
        if (lane == 0) { q0[wrp]=shm; q1[wrp]=swn; q2[wrp]=srw; q3[wrp]=snp; }
        __syncthreads();
        if (tid == 0) {
            double thm=0.0, twn=0.0, trw=0.0; int tnp=0;
#pragma unroll
            for (int i = 0; i < 8; i++) { thm+=q0[i]; twn+=q1[i]; trw+=q2[i]; tnp+=q3[i]; }
            double hml = (tnp > 0) ? (-thm / (double)(tnp < 1 ? 1 : tnp)) : -thm;
            double whl = twn / fmax(trw, 1.0);
            out[0] = (float)(hml + whl);
            d_done_ctr = 0u;
        }
    }
}

// =====================================================================
// base: streaming focal base term. 2560 blocks x 256 thr x 8 float4.
// (identical compute shape to the 20.4us-measured R7 kernel)
// =====================================================================
__global__ void __launch_bounds__(256) base_kernel(const float4* __restrict__ hm4,
                                                   float* __restrict__ out) {
    int idx = blockIdx.x * (256*8) + threadIdx.x;
    float4 v[8];
#pragma unroll
    for (int u = 0; u < 8; u++) v[u] = __ldg(&hm4[idx + u*256]);
    float lsum = 0.0f;
#pragma unroll
    for (int u = 0; u < 8; u++) {
        float p;
        lsum += focal_neg_base(v[u].x, p);
        lsum += focal_neg_base(v[u].y, p);
        lsum += focal_neg_base(v[u].z, p);
        lsum += focal_neg_base(v[u].w, p);
    }
    commit_and_maybe_finalize(blockIdx.x, lsum, 0.0f, 0.0f, 0, out);
}

// =====================================================================
// sparse: inline per-image prep (redundant per block) + corrections +
// wh/IoU for 2 rows. 1024 blocks x 256 threads.
// =====================================================================
__global__ void __launch_bounds__(256)
sparse_kernel(const float* __restrict__ hm,
              const float* __restrict__ wh,
              const float* __restrict__ tgt,
              const void*  __restrict__ mraw,
              float* __restrict__ out) {
    int sid = blockIdx.x;
    int b  = sid >> 6;
    int y0 = (sid & 63) * 2;
    int tid = threadIdx.x;
    int lane = tid & 31;
    int wrp  = tid >> 5;
    int half = tid >> 7;          // 0 or 1
    int x    = tid & 127;
    int k2   = tid & 127;         // sorted-slot index this thread serves

    // ---------------- shared state ----------------
    __shared__ int   s_gt1, s_off4;
    __shared__ int   smask[KBOX];
    __shared__ float skey[KBOX];
    __shared__ int   sperm[KBOX];
    __shared__ float s_al0;
    __shared__ float sdy[KBOX], sdx[KBOX];
    __shared__ float sx1[KBOX], sy1s[KBOX], sx2[KBOX], sy2s[KBOX];
    __shared__ float scoef[KBOX], si2sx[KBOX];
    __shared__ short scx[KBOX], swr[KBOX], scls[KBOX];
    __shared__ float sgy2[2][KBOX];
    __shared__ short slist2[2][KBOX];
    __shared__ int   s_n2[2];

    // ---------------- inline prep: dtype sniff ----------------
    if (tid == 0) { s_gt1 = 0; s_off4 = 0; }
    __syncthreads();
    {
        const uint8_t* b8 = (const uint8_t*)mraw;
        int gt1 = 0, off4 = 0;
#pragma unroll
        for (int c = 0; c < NB/256; c++) {
            int i = c*256 + tid;
            uint8_t vv = b8[i];
            gt1  |= (vv > 1);
            off4 |= (vv != 0) && ((i & 3) != 0);
        }
        if (gt1)  atomicOr(&s_gt1, 1);
        if (off4) atomicOr(&s_off4, 1);
    }
    __syncthreads();
    int u8mode = (!s_gt1) && s_off4;
    if (tid < KBOX) {
        int i = b*KBOX + tid;
        smask[tid] = u8mode ? (((const uint8_t*)mraw)[i] != 0)
                            : (((const uint32_t*)mraw)[i] != 0u);
    }
    __syncthreads();
    if (tid < KBOX) {
        const float* t = tgt + (size_t)(b*KBOX + tid)*5;
        float x1 = t[1], y1 = t[2], x2 = t[3], y2 = t[4];
        float area = (x2 - x1) * (y2 - y1);
        skey[tid] = smask[tid] ? __logf(area) : -INFINITY;
    }
    __syncthreads();
    if (tid < KBOX) {
        float key = skey[tid];
        int rank = 0;
#pragma unroll 16
        for (int j = 0; j < KBOX; j++) {
            float kj = skey[j];
            rank += (kj > key) || (kj == key && j < tid);
        }
        sperm[rank] = tid;
    }
    __syncthreads();
    if (tid == 0) {
        int o0 = sperm[0];
        s_al0 = smask[o0] ? skey[o0] : 0.0f;
    }
    __syncthreads();

    // ---------------- per sorted slot k2 (both halves recompute) --------
    {
        int o = sperm[k2];
        const float* to = tgt + (size_t)(b*KBOX + o)*5;
        float clsf = to[0];
        float ox1 = to[1], oy1 = to[2], ox2 = to[3], oy2 = to[4];
        int v = smask[o];
        float keyo = skey[o];

        float fx1 = fminf(fmaxf(ox1 * 0.25f, 0.0f), (float)(OW-1));
        float fy1 = fminf(fmaxf(oy1 * 0.25f, 0.0f), (float)(OH-1));
        float fx2 = fminf(fmaxf(ox2 * 0.25f, 0.0f), (float)(OW-1));
        float fy2 = fminf(fmaxf(oy2 * 0.25f, 0.0f), (float)(OH-1));
        float feat_h = fy2 - fy1;
        float feat_w = fx2 - fx1;

        int cx = (int)(((ox1 + ox2) * 0.5f) * 0.25f);
        int cy = (int)(((oy1 + oy2) * 0.5f) * 0.25f);
        int hr = (int)((feat_h * 0.5f) * 0.54f);
        int wr = (int)((feat_w * 0.5f) * 0.54f);
        float sy = (float)(2*hr + 1) / 6.0f;
        float sx = (float)(2*wr + 1) / 6.0f;
        float i2sy = 1.0f / (2.0f * sy * sy);
        float i2sx = 1.0f / (2.0f * sx * sx);

        int act = v && (cx >= 0) && (cx < OW) && (cy >= 0) && (cy < OH);

        if (tid < KBOX) {
            // y-direction div partial + box data stores + row gaussians
            float sgy = 0.0f;
            if (act) {
                int ya = max(0, cy - hr), yb = min(OH-1, cy + hr);
                for (int yy = ya; yy <= yb; yy++) {
                    float d = (float)(yy - cy);
                    sgy += __expf(-(d*d) * i2sy);
                }
            }
            sdy[k2] = sgy;
            sx1[k2] = ox1; sy1s[k2] = oy1; sx2[k2] = ox2; sy2s[k2] = oy2;
            si2sx[k2] = i2sx;
            scx[k2] = (short)cx; swr[k2] = (short)wr; scls[k2] = (short)clsf;
#pragma unroll
            for (int r = 0; r < 2; r++) {
                int dy = y0 + r - cy;
                int rc = act && (abs(dy) <= hr);
                sgy2[r][k2] = rc ? __expf(-(float)(dy*dy) * i2sy) : 0.0f;
            }
        } else {
            // x-direction div partial
            float sgx = 0.0f;
            if (act) {
                int xa = max(0, cx - wr), xb = min(OW-1, cx + wr);
                for (int xx = xa; xx <= xb; xx++) {
                    float d = (float)(xx - cx);
                    sgx += __expf(-(d*d) * i2sx);
                }
            }
            sdx[k2] = sgx;
        }
        __syncthreads();
        if (tid < KBOX) {
            float divs = act ? (sdy[k2] * sdx[k2]) : 0.0f;
            float al = v ? keyo : 0.0f;
            float factor = 2.0f - al / (s_al0 + 1e-7f);
            scoef[k2] = act ? (factor / (divs + 1e-7f)) : 0.0f;
        }
    }
    __syncthreads();

    // ---------------- row lists (warps 0 and 4) ----------------
    if (wrp == 0 || wrp == 4) {
        int row = (wrp == 4);
        int nn = 0;
#pragma unroll
        for (int chunk = 0; chunk < 4; chunk++) {
            int j = chunk*32 + lane;
            bool p = sgy2[row][j] > 0.0f;
            unsigned mb = __ballot_sync(0xffffffffu, p);
            int pos = nn + __popc(mb & ((1u << lane) - 1u));
            if (p) slist2[row][pos] = (short)j;
            nn += __popc(mb);
        }
        if (lane == 0) s_n2[row] = nn;
    }
    __syncthreads();

    int y = y0 + half;
    int n = s_n2[half];
    const short* mylist = slist2[half];
    const float* mysgy  = sgy2[half];

    // ---------------- coverage + winner ----------------
    unsigned covm[4] = {0u,0u,0u,0u};
    int e_w = -1;
    for (int e = 0; e < n; e++) {
        int j = mylist[e];
        int dx = x - scx[j];
        if (abs(dx) <= swr[j]) {
            covm[e >> 5] |= 1u << (e & 31);
            e_w = e;
        }
    }

    float lsum = 0.0f, lwhn = 0.0f, lrw = 0.0f;
    int   lnp  = 0;
    const float* hmr = hm + (((size_t)b*NUMC)*OH + y)*OW + x;

    // ---------------- footprint corrections ----------------
    for (int e = 0; e < n; e++) {
        if (!((covm[e >> 5] >> (e & 31)) & 1u)) continue;
        int j = mylist[e];
        int c = scls[j];
        float dxf = (float)(x - scx[j]);
        float g = mysgy[j] * __expf(-dxf*dxf * si2sx[j]);
        bool rep = true;
        for (int e2 = 0; e2 < n; e2++) {
            if (e2 == e) continue;
            if (!((covm[e2 >> 5] >> (e2 & 31)) & 1u)) continue;
            int j2 = mylist[e2];
            if (scls[j2] != c) continue;
            float dx2 = (float)(x - scx[j2]);
            float g2 = mysgy[j2] * __expf(-dx2*dx2 * si2sx[j2]);
            if (g2 > g || (g2 == g && e2 < e)) { rep = false; break; }
        }
        if (!rep) continue;
        float xv = hmr[(size_t)c * PLANE];
        float p;
        float u = focal_neg_base(xv, p);
        if (g == 1.0f) {
            float omp = 1.0f - p;
            float vv = __logf(p) * omp * omp;
            lsum += vv - u;
            lnp++;
        } else {
            float omh = 1.0f - g;
            float w4 = omh * omh; w4 *= w4;
            lsum += u * (w4 - 1.0f);
        }
    }

    // ---------------- wh / IoU at winner pixels ----------------
    if (e_w >= 0) {
        int j = mylist[e_w];
        float dxf = (float)(x - scx[j]);
        float g = mysgy[j] * __expf(-dxf*dxf * si2sx[j]);
        float rw = g * scoef[j];
        size_t pbase = (((size_t)b*4)*OH + y)*OW + x;
        float pl = wh[pbase            ] * 16.0f;
        float pt = wh[pbase +   PLANE  ] * 16.0f;
        float pr = wh[pbase + 2*PLANE  ] * 16.0f;
        float pb = wh[pbase + 3*PLANE  ] * 16.0f;
        float xs = (float)x * 4.0f, ys = (float)y * 4.0f;
        float tl = xs - sx1[j];
        float tt = ys - sy1s[j];
        float tr = sx2[j] - xs;
        float tb = sy2s[j] - ys;
        float ta = (tl + tr) * (tt + tb);
        float pa = (pl + pr) * (pt + pb);
        float wi = fminf(pl, tl) + fminf(pr, tr);
        float hi = fminf(pt, tt) + fminf(pb, tb);
        float ai = wi * hi;
        float au = ta + pa - ai;
        float iou = (ai + 1.0f) / (au + 1.0f);
        lwhn = (rw > 0.0f) ? (1.0f - iou) * rw : 0.0f;
        lrw = rw;
    }

    commit_and_maybe_finalize(NBASE + sid, lsum, lwhn, lrw, lnp, out);
}

extern "C" void kernel_launch(void* const* d_in, const int* in_sizes, int n_in,
                              void* d_out, int out_size) {
    const float* hm   = (const float*)d_in[0];
    const float* wh   = (const float*)d_in[1];
    const float* tgt  = (const float*)d_in[2];
    const void*  mask = (const void*)d_in[3];
    float* out = (float*)d_out;
    (void)in_sizes; (void)n_in; (void)out_size;

    base_kernel<<<NBASE, 256>>>((const float4*)hm, out);
    sparse_kernel<<<NSPA, 256>>>(hm, wh, tgt, mask, out);
}

// round 13
// speedup vs baseline: 1.2995x; 1.1532x over previous
#include <cuda_runtime.h>
#include <math.h>
#include <stdint.h>

#define BATCH 16
#define KBOX  128
#define NUMC  80
#define OH    128
#define OW    128
#define NB    (BATCH*KBOX)
#define PLANE (OH*OW)
#define NBASE 2560                 // (16*80*128*128/4) / (256*8)
#define NSPA  1024                 // 2 rows per block
#define NTOT  (NBASE + NSPA)       // 3584

// ---- per-box scratch (sorted order) ----
__device__ float d_bx1[NB], d_by1[NB], d_bx2[NB], d_by2[NB];
__device__ float d_i2sx_g[NB], d_coef_g[NB];
__device__ float d_gy_all[NB*2]; // unused placeholder (kept small)
__device__ float d_i2sy_g[NB];
__device__ int   d_cls_g[NB], d_cx_g[NB], d_cy_g[NB], d_hr_g[NB], d_wr_g[NB], d_act_g[NB];

// ---- per-block partial slots + ticket (self-resetting) ----
__device__ float d_part_hm[NTOT], d_part_whn[NTOT], d_part_rw[NTOT];
__device__ int   d_part_np[NTOT];
__device__ unsigned int d_done_ctr;

// u(x) = log(1 - clip(sigmoid(x))) * clip(sigmoid(x))^2   (3 MUFU)
__device__ __forceinline__ float focal_neg_base(float xv, float& p_out) {
    float t = __expf(-xv);
    float p = __fdividef(1.0f, 1.0f + t);
    p = fminf(fmaxf(p, 1e-4f), 0.9999f);
    p_out = p;
    float omp = 1.0f - p;
    return __logf(omp) * p * p;
}

// block(256thr) reduce -> slot; globally-last block finalizes + resets.
__device__ __forceinline__ void commit_and_maybe_finalize(
        int slot, float lsum, float lwhn, float lrw, int lnp, float* out) {
    int tid = threadIdx.x, lane = tid & 31, wrp = tid >> 5;
    for (int off = 16; off; off >>= 1) {
        lsum += __shfl_down_sync(0xffffffffu, lsum, off);
        lwhn += __shfl_down_sync(0xffffffffu, lwhn, off);
        lrw  += __shfl_down_sync(0xffffffffu, lrw,  off);
        lnp  += __shfl_down_sync(0xffffffffu, lnp,  off);
    }
    __shared__ float r0[8], r1[8], r2[8];
    __shared__ int   r3[8];
    if (lane == 0) { r0[wrp]=lsum; r1[wrp]=lwhn; r2[wrp]=lrw; r3[wrp]=lnp; }
    __syncthreads();
    if (tid == 0) {
        float a=0.f, c1=0.f, c2=0.f; int np=0;
#pragma unroll
        for (int i = 0; i < 8; i++) { a+=r0[i]; c1+=r1[i]; c2+=r2[i]; np+=r3[i]; }
        d_part_hm[slot]  = a;
        d_part_whn[slot] = c1;
        d_part_rw[slot]  = c2;
        d_part_np[slot]  = np;
    }
    __shared__ bool amLast;
    __threadfence();
    __syncthreads();
    if (tid == 0)
        amLast = (atomicAdd(&d_done_ctr, 1u) == (unsigned)(NTOT - 1));
    __syncthreads();
    if (amLast) {
        double shm = 0.0, swn = 0.0, srw = 0.0;
        int snp = 0;
        for (int i = tid; i < NTOT; i += 256) {
            shm += (double)d_part_hm[i];
            swn += (double)d_part_whn[i];
            srw += (double)d_part_rw[i];
            snp += d_part_np[i];
        }
        for (int off = 16; off; off >>= 1) {
            shm += __shfl_down_sync(0xffffffffu, shm, off);
            swn += __shfl_down_sync(0xffffffffu, swn, off);
            srw += __shfl_down_sync(0xffffffffu, srw, off);
            snp += __shfl_down_sync(0xffffffffu, snp, off);
        }
        __shared__ double q0[8], q1[8], q2[8];
        __shared__ int    q3[8];
        if (lane == 0) { q0[wrp]=shm; q1[wrp]=swn; q2[wrp]=srw; q3[wrp]=snp; }
        __syncthreads();
        if (tid == 0) {
            double thm=0.0, twn=0.0, trw=0.0; int tnp=0;
#pragma unroll
            for (int i = 0; i < 8; i++) { thm+=q0[i]; twn+=q1[i]; trw+=q2[i]; tnp+=q3[i]; }
            double hml = (tnp > 0) ? (-thm / (double)(tnp < 1 ? 1 : tnp)) : -thm;
            double whl = twn / fmax(trw, 1.0);
            out[0] = (float)(hml + whl);
            d_done_ctr = 0u;
        }
    }
}

// =====================================================================
// base: blocks 0..15 run prep for image bid first (once each), then all
// 2560 blocks stream 2048 float4 of the focal base term.
// =====================================================================
__global__ void __launch_bounds__(256)
base_kernel(const float4* __restrict__ hm4,
            const float* __restrict__ tgt,
            const void*  __restrict__ mraw,
            float* __restrict__ out) {
    int bid = blockIdx.x;
    int tid = threadIdx.x;

    if (bid < BATCH) {
        // -------- prep for image b = bid (256 threads, split y/x sums) ----
        int b = bid;
        int k2 = tid & 127;
        __shared__ int   s_gt1, s_off4;
        __shared__ int   smask[KBOX];
        __shared__ float skey[KBOX];
        __shared__ int   sperm[KBOX];
        __shared__ float s_al0;
        __shared__ float sdy[KBOX], sdx[KBOX];

        if (tid == 0) { s_gt1 = 0; s_off4 = 0; }
        __syncthreads();
        {
            const uint8_t* b8 = (const uint8_t*)mraw;
            int gt1 = 0, off4 = 0;
#pragma unroll
            for (int c = 0; c < NB/256; c++) {
                int i = c*256 + tid;
                uint8_t vv = b8[i];
                gt1  |= (vv > 1);
                off4 |= (vv != 0) && ((i & 3) != 0);
            }
            if (gt1)  atomicOr(&s_gt1, 1);
            if (off4) atomicOr(&s_off4, 1);
        }
        __syncthreads();
        int u8mode = (!s_gt1) && s_off4;
        if (tid < KBOX) {
            int i = b*KBOX + tid;
            smask[tid] = u8mode ? (((const uint8_t*)mraw)[i] != 0)
                                : (((const uint32_t*)mraw)[i] != 0u);
        }
        __syncthreads();
        if (tid < KBOX) {
            const float* t = tgt + (size_t)(b*KBOX + tid)*5;
            float x1 = t[1], y1 = t[2], x2 = t[3], y2 = t[4];
            float area = (x2 - x1) * (y2 - y1);
            skey[tid] = smask[tid] ? __logf(area) : -INFINITY;
        }
        __syncthreads();
        if (tid < KBOX) {
            float key = skey[tid];
            int rank = 0;
#pragma unroll 16
            for (int j = 0; j < KBOX; j++) {
                float kj = skey[j];
                rank += (kj > key) || (kj == key && j < tid);
            }
            sperm[rank] = tid;
        }
        __syncthreads();
        if (tid == 0) {
            int o0 = sperm[0];
            s_al0 = smask[o0] ? skey[o0] : 0.0f;
        }
        __syncthreads();
        {
            int o = sperm[k2];
            const float* to = tgt + (size_t)(b*KBOX + o)*5;
            float clsf = to[0];
            float ox1 = to[1], oy1 = to[2], ox2 = to[3], oy2 = to[4];
            int v = smask[o];
            float keyo = skey[o];

            float fx1 = fminf(fmaxf(ox1 * 0.25f, 0.0f), (float)(OW-1));
            float fy1 = fminf(fmaxf(oy1 * 0.25f, 0.0f), (float)(OH-1));
            float fx2 = fminf(fmaxf(ox2 * 0.25f, 0.0f), (float)(OW-1));
            float fy2 = fminf(fmaxf(oy2 * 0.25f, 0.0f), (float)(OH-1));
            float feat_h = fy2 - fy1;
            float feat_w = fx2 - fx1;

            int cx = (int)(((ox1 + ox2) * 0.5f) * 0.25f);
            int cy = (int)(((oy1 + oy2) * 0.5f) * 0.25f);
            int hr = (int)((feat_h * 0.5f) * 0.54f);
            int wr = (int)((feat_w * 0.5f) * 0.54f);
            float sy = (float)(2*hr + 1) / 6.0f;
            float sx = (float)(2*wr + 1) / 6.0f;
            float i2sy = 1.0f / (2.0f * sy * sy);
            float i2sx = 1.0f / (2.0f * sx * sx);

            int act = v && (cx >= 0) && (cx < OW) && (cy >= 0) && (cy < OH);

            if (tid < KBOX) {
                float sgy = 0.0f;
                if (act) {
                    int ya = max(0, cy - hr), yb = min(OH-1, cy + hr);
                    for (int yy = ya; yy <= yb; yy++) {
                        float d = (float)(yy - cy);
                        sgy += __expf(-(d*d) * i2sy);
                    }
                }
                sdy[k2] = sgy;
            } else {
                float sgx = 0.0f;
                if (act) {
                    int xa = max(0, cx - wr), xb = min(OW-1, cx + wr);
                    for (int xx = xa; xx <= xb; xx++) {
                        float d = (float)(xx - cx);
                        sgx += __expf(-(d*d) * i2sx);
                    }
                }
                sdx[k2] = sgx;
            }
            __syncthreads();
            if (tid < KBOX) {
                float divs = act ? (sdy[k2] * sdx[k2]) : 0.0f;
                float al = v ? keyo : 0.0f;
                float factor = 2.0f - al / (s_al0 + 1e-7f);
                float coef = act ? (factor / (divs + 1e-7f)) : 0.0f;

                int idx = b*KBOX + k2;
                d_bx1[idx] = ox1; d_by1[idx] = oy1; d_bx2[idx] = ox2; d_by2[idx] = oy2;
                d_i2sy_g[idx] = i2sy; d_i2sx_g[idx] = i2sx; d_coef_g[idx] = coef;
                d_cls_g[idx] = (int)clsf; d_cx_g[idx] = cx; d_cy_g[idx] = cy;
                d_hr_g[idx] = hr; d_wr_g[idx] = wr; d_act_g[idx] = act;
            }
        }
        __syncthreads();
    }

    // -------- streaming focal base term (all blocks) --------
    int idx = bid * (256*8) + tid;
    float4 v[8];
#pragma unroll
    for (int u = 0; u < 8; u++) v[u] = __ldg(&hm4[idx + u*256]);
    float lsum = 0.0f;
#pragma unroll
    for (int u = 0; u < 8; u++) {
        float p;
        lsum += focal_neg_base(v[u].x, p);
        lsum += focal_neg_base(v[u].y, p);
        lsum += focal_neg_base(v[u].z, p);
        lsum += focal_neg_base(v[u].w, p);
    }
    commit_and_maybe_finalize(bid, lsum, 0.0f, 0.0f, 0, out);
}

// =====================================================================
// sparse: corrections + wh/IoU for 2 rows. 1024 blocks x 256 threads.
// Reads prep results written by base_kernel (stream-ordered).
// =====================================================================
__global__ void __launch_bounds__(256)
sparse_kernel(const float* __restrict__ hm,
              const float* __restrict__ wh,
              float* __restrict__ out) {
    int sid = blockIdx.x;
    int b  = sid >> 6;
    int y0 = (sid & 63) * 2;
    int tid = threadIdx.x;
    int lane = tid & 31;
    int wrp  = tid >> 5;
    int half = tid >> 7;          // 0 or 1
    int x    = tid & 127;

    __shared__ float sx1[KBOX], sy1s[KBOX], sx2[KBOX], sy2s[KBOX];
    __shared__ float scoef[KBOX], si2sx[KBOX];
    __shared__ short scx[KBOX], swr[KBOX], scls[KBOX];
    __shared__ float sgy2[2][KBOX];
    __shared__ short slist2[2][KBOX];
    __shared__ int   s_n2[2];

    if (tid < KBOX) {
        int base = b*KBOX + tid;
        float i2sy = d_i2sy_g[base];
        int cy = d_cy_g[base], hr = d_hr_g[base], act = d_act_g[base];
        sx1[tid] = d_bx1[base]; sy1s[tid] = d_by1[base];
        sx2[tid] = d_bx2[base]; sy2s[tid] = d_by2[base];
        scoef[tid] = d_coef_g[base]; si2sx[tid] = d_i2sx_g[base];
        scx[tid] = (short)d_cx_g[base]; swr[tid] = (short)d_wr_g[base];
        scls[tid] = (short)d_cls_g[base];
#pragma unroll
        for (int r = 0; r < 2; r++) {
            int dy = y0 + r - cy;
            int rc = act && (abs(dy) <= hr);
            sgy2[r][tid] = rc ? __expf(-(float)(dy*dy) * i2sy) : 0.0f;
        }
    }
    __syncthreads();
    if (wrp == 0 || wrp == 4) {
        int row = (wrp == 4);
        int nn = 0;
#pragma unroll
        for (int chunk = 0; chunk < 4; chunk++) {
            int j = chunk*32 + lane;
            bool p = sgy2[row][j] > 0.0f;
            unsigned mb = __ballot_sync(0xffffffffu, p);
            int pos = nn + __popc(mb & ((1u << lane) - 1u));
            if (p) slist2[row][pos] = (short)j;
            nn += __popc(mb);
        }
        if (lane == 0) s_n2[row] = nn;
    }
    __syncthreads();

    int y = y0 + half;
    int n = s_n2[half];
    const short* mylist = slist2[half];
    const float* mysgy  = sgy2[half];

    unsigned covm[4] = {0u,0u,0u,0u};
    int e_w = -1;
    for (int e = 0; e < n; e++) {
        int j = mylist[e];
        int dx = x - scx[j];
        if (abs(dx) <= swr[j]) {
            covm[e >> 5] |= 1u << (e & 31);
            e_w = e;
        }
    }

    float lsum = 0.0f, lwhn = 0.0f, lrw = 0.0f;
    int   lnp  = 0;
    const float* hmr = hm + (((size_t)b*NUMC)*OH + y)*OW + x;

    for (int e = 0; e < n; e++) {
        if (!((covm[e >> 5] >> (e & 31)) & 1u)) continue;
        int j = mylist[e];
        int c = scls[j];
        float dxf = (float)(x - scx[j]);
        float g = mysgy[j] * __expf(-dxf*dxf * si2sx[j]);
        bool rep = true;
        for (int e2 = 0; e2 < n; e2++) {
            if (e2 == e) continue;
            if (!((covm[e2 >> 5] >> (e2 & 31)) & 1u)) continue;
            int j2 = mylist[e2];
            if (scls[j2] != c) continue;
            float dx2 = (float)(x - scx[j2]);
            float g2 = mysgy[j2] * __expf(-dx2*dx2 * si2sx[j2]);
            if (g2 > g || (g2 == g && e2 < e)) { rep = false; break; }
        }
        if (!rep) continue;
        float xv = hmr[(size_t)c * PLANE];
        float p;
        float u = focal_neg_base(xv, p);
        if (g == 1.0f) {
            float omp = 1.0f - p;
            float vv = __logf(p) * omp * omp;
            lsum += vv - u;
            lnp++;
        } else {
            float omh = 1.0f - g;
            float w4 = omh * omh; w4 *= w4;
            lsum += u * (w4 - 1.0f);
        }
    }

    if (e_w >= 0) {
        int j = mylist[e_w];
        float dxf = (float)(x - scx[j]);
        float g = mysgy[j] * __expf(-dxf*dxf * si2sx[j]);
        float rw = g * scoef[j];
        size_t pbase = (((size_t)b*4)*OH + y)*OW + x;
        float pl = wh[pbase            ] * 16.0f;
        float pt = wh[pbase +   PLANE  ] * 16.0f;
        float pr = wh[pbase + 2*PLANE  ] * 16.0f;
        float pb = wh[pbase + 3*PLANE  ] * 16.0f;
        float xs = (float)x * 4.0f, ys = (float)y * 4.0f;
        float tl = xs - sx1[j];
        float tt = ys - sy1s[j];
        float tr = sx2[j] - xs;
        float tb = sy2s[j] - ys;
        float ta = (tl + tr) * (tt + tb);
        float pa = (pl + pr) * (pt + pb);
        float wi = fminf(pl, tl) + fminf(pr, tr);
        float hi = fminf(pt, tt) + fminf(pb, tb);
        float ai = wi * hi;
        float au = ta + pa - ai;
        float iou = (ai + 1.0f) / (au + 1.0f);
        lwhn = (rw > 0.0f) ? (1.0f - iou) * rw : 0.0f;
        lrw = rw;
    }

    commit_and_maybe_finalize(NBASE + sid, lsum, lwhn, lrw, lnp, out);
}

extern "C" void kernel_launch(void* const* d_in, const int* in_sizes, int n_in,
                              void* d_out, int out_size) {
    const float* hm   = (const float*)d_in[0];
    const float* wh   = (const float*)d_in[1];
    const float* tgt  = (const float*)d_in[2];
    const void*  mask = (const void*)d_in[3];
    float* out = (float*)d_out;
    (void)in_sizes; (void)n_in; (void)out_size;

    base_kernel<<<NBASE, 256>>>((const float4*)hm, tgt, mask, out);
    sparse_kernel<<<NSPA, 256>>>(hm, wh, out);
}

// round 14
// speedup vs baseline: 1.5917x; 1.2249x over previous
#include <cuda_runtime.h>
#include <math.h>
#include <stdint.h>

#define BATCH 16
#define KBOX  128
#define NUMC  80
#define OH    128
#define OW    128
#define NB    (BATCH*KBOX)
#define PLANE (OH*OW)
#define NBASE 2560                 // (16*80*128*128/4) / (256*8)
#define NSPA  (OH*BATCH)           // 2048

// ---- per-box scratch (sorted order), written by base prep branch ----
__device__ float d_bx1[NB], d_by1[NB], d_bx2[NB], d_by2[NB];
__device__ float d_i2sy_g[NB], d_i2sx_g[NB], d_coef_g[NB];
__device__ int   d_cls_g[NB], d_cx_g[NB], d_cy_g[NB], d_hr_g[NB], d_wr_g[NB], d_act_g[NB];

// ---- global accumulators + sparse ticket (self-resetting) ----
__device__ double d_acc_hm;
__device__ double d_acc_whn;
__device__ double d_acc_rw;
__device__ int    d_acc_np;
__device__ unsigned int d_spa_ctr;

// u(x) = log(1 - clip(sigmoid(x))) * clip(sigmoid(x))^2   (3 MUFU)
__device__ __forceinline__ float focal_neg_base(float xv, float& p_out) {
    float t = __expf(-xv);
    float p = __fdividef(1.0f, 1.0f + t);
    p = fminf(fmaxf(p, 1e-4f), 0.9999f);
    p_out = p;
    float omp = 1.0f - p;
    return __logf(omp) * p * p;
}

// =====================================================================
// base: blocks 0..15 run prep for image bid first (once each), then all
// 2560 blocks stream 2048 float4 of the focal base term. R4-style commit.
// =====================================================================
__global__ void __launch_bounds__(256)
base_kernel(const float4* __restrict__ hm4,
            const float* __restrict__ tgt,
            const void*  __restrict__ mraw) {
    int bid = blockIdx.x;
    int tid = threadIdx.x;

    if (bid < BATCH) {
        // -------- prep for image b = bid (256 threads, split y/x sums) ----
        int b = bid;
        int k2 = tid & 127;
        __shared__ int   s_gt1, s_off4;
        __shared__ int   smask[KBOX];
        __shared__ float skey[KBOX];
        __shared__ int   sperm[KBOX];
        __shared__ float s_al0;
        __shared__ float sdy[KBOX], sdx[KBOX];

        if (tid == 0) { s_gt1 = 0; s_off4 = 0; }
        __syncthreads();
        {
            const uint8_t* b8 = (const uint8_t*)mraw;
            int gt1 = 0, off4 = 0;
#pragma unroll
            for (int c = 0; c < NB/256; c++) {
                int i = c*256 + tid;
                uint8_t vv = b8[i];
                gt1  |= (vv > 1);
                off4 |= (vv != 0) && ((i & 3) != 0);
            }
            if (gt1)  atomicOr(&s_gt1, 1);
            if (off4) atomicOr(&s_off4, 1);
        }
        __syncthreads();
        int u8mode = (!s_gt1) && s_off4;
        if (tid < KBOX) {
            int i = b*KBOX + tid;
            smask[tid] = u8mode ? (((const uint8_t*)mraw)[i] != 0)
                                : (((const uint32_t*)mraw)[i] != 0u);
        }
        __syncthreads();
        if (tid < KBOX) {
            const float* t = tgt + (size_t)(b*KBOX + tid)*5;
            float x1 = t[1], y1 = t[2], x2 = t[3], y2 = t[4];
            float area = (x2 - x1) * (y2 - y1);
            skey[tid] = smask[tid] ? __logf(area) : -INFINITY;
        }
        __syncthreads();
        if (tid < KBOX) {
            float key = skey[tid];
            int rank = 0;
#pragma unroll 16
            for (int j = 0; j < KBOX; j++) {
                float kj = skey[j];
                rank += (kj > key) || (kj == key && j < tid);
            }
            sperm[rank] = tid;
        }
        __syncthreads();
        if (tid == 0) {
            int o0 = sperm[0];
            s_al0 = smask[o0] ? skey[o0] : 0.0f;
        }
        __syncthreads();
        {
            int o = sperm[k2];
            const float* to = tgt + (size_t)(b*KBOX + o)*5;
            float clsf = to[0];
            float ox1 = to[1], oy1 = to[2], ox2 = to[3], oy2 = to[4];
            int v = smask[o];
            float keyo = skey[o];

            float fx1 = fminf(fmaxf(ox1 * 0.25f, 0.0f), (float)(OW-1));
            float fy1 = fminf(fmaxf(oy1 * 0.25f, 0.0f), (float)(OH-1));
            float fx2 = fminf(fmaxf(ox2 * 0.25f, 0.0f), (float)(OW-1));
            float fy2 = fminf(fmaxf(oy2 * 0.25f, 0.0f), (float)(OH-1));
            float feat_h = fy2 - fy1;
            float feat_w = fx2 - fx1;

            int cx = (int)(((ox1 + ox2) * 0.5f) * 0.25f);
            int cy = (int)(((oy1 + oy2) * 0.5f) * 0.25f);
            int hr = (int)((feat_h * 0.5f) * 0.54f);
            int wr = (int)((feat_w * 0.5f) * 0.54f);
            float sy = (float)(2*hr + 1) / 6.0f;
            float sx = (float)(2*wr + 1) / 6.0f;
            float i2sy = 1.0f / (2.0f * sy * sy);
            float i2sx = 1.0f / (2.0f * sx * sx);

            int act = v && (cx >= 0) && (cx < OW) && (cy >= 0) && (cy < OH);

            if (tid < KBOX) {
                float sgy = 0.0f;
                if (act) {
                    int ya = max(0, cy - hr), yb = min(OH-1, cy + hr);
                    for (int yy = ya; yy <= yb; yy++) {
                        float d = (float)(yy - cy);
                        sgy += __expf(-(d*d) * i2sy);
                    }
                }
                sdy[k2] = sgy;
            } else {
                float sgx = 0.0f;
                if (act) {
                    int xa = max(0, cx - wr), xb = min(OW-1, cx + wr);
                    for (int xx = xa; xx <= xb; xx++) {
                        float d = (float)(xx - cx);
                        sgx += __expf(-(d*d) * i2sx);
                    }
                }
                sdx[k2] = sgx;
            }
            __syncthreads();
            if (tid < KBOX) {
                float divs = act ? (sdy[k2] * sdx[k2]) : 0.0f;
                float al = v ? keyo : 0.0f;
                float factor = 2.0f - al / (s_al0 + 1e-7f);
                float coef = act ? (factor / (divs + 1e-7f)) : 0.0f;

                int idx = b*KBOX + k2;
                d_bx1[idx] = ox1; d_by1[idx] = oy1; d_bx2[idx] = ox2; d_by2[idx] = oy2;
                d_i2sy_g[idx] = i2sy; d_i2sx_g[idx] = i2sx; d_coef_g[idx] = coef;
                d_cls_g[idx] = (int)clsf; d_cx_g[idx] = cx; d_cy_g[idx] = cy;
                d_hr_g[idx] = hr; d_wr_g[idx] = wr; d_act_g[idx] = act;
            }
        }
        __syncthreads();
    }

    // -------- streaming focal base term (all blocks) --------
    int idx = bid * (256*8) + tid;
    float4 v[8];
#pragma unroll
    for (int u = 0; u < 8; u++) v[u] = __ldg(&hm4[idx + u*256]);
    float lsum = 0.0f;
#pragma unroll
    for (int u = 0; u < 8; u++) {
        float p;
        lsum += focal_neg_base(v[u].x, p);
        lsum += focal_neg_base(v[u].y, p);
        lsum += focal_neg_base(v[u].z, p);
        lsum += focal_neg_base(v[u].w, p);
    }

    for (int off = 16; off; off >>= 1)
        lsum += __shfl_down_sync(0xffffffffu, lsum, off);
    __shared__ float r[8];
    int w = tid >> 5;
    if ((tid & 31) == 0) r[w] = lsum;
    __syncthreads();
    if (tid == 0) {
        float a = 0.0f;
#pragma unroll
        for (int i = 0; i < 8; i++) a += r[i];
        atomicAdd(&d_acc_hm, (double)a);
    }
}

// =====================================================================
// sparse: EXACT R4 shape. grid=(OH, BATCH), 128 threads, 1 row/block.
// Last sparse block (ticket) finalizes out[0] and resets accumulators.
// =====================================================================
__global__ void __launch_bounds__(128)
sparse_kernel(const float* __restrict__ hm,
              const float* __restrict__ wh,
              float* __restrict__ out) {
    int y = blockIdx.x, b = blockIdx.y, x = threadIdx.x;
    int m = threadIdx.x;
    int lane = m & 31;

    __shared__ float sgy[KBOX];
    __shared__ float sx1[KBOX], sy1s[KBOX], sx2[KBOX], sy2s[KBOX];
    __shared__ float scoef[KBOX], si2sx[KBOX];
    __shared__ int   scx[KBOX], swr[KBOX], scls[KBOX];
    __shared__ short slist[KBOX];
    __shared__ int   s_n;

    int base = b*KBOX + m;
    {
        float i2sy = d_i2sy_g[base];
        int cy = d_cy_g[base], hr = d_hr_g[base], act = d_act_g[base];
        int dy = y - cy;
        int rowcov = act && (abs(dy) <= hr);
        sgy[m] = rowcov ? __expf(-(float)(dy*dy) * i2sy) : 0.0f;
        sx1[m] = d_bx1[base]; sy1s[m] = d_by1[base];
        sx2[m] = d_bx2[base]; sy2s[m] = d_by2[base];
        scoef[m] = d_coef_g[base]; si2sx[m] = d_i2sx_g[base];
        scx[m] = d_cx_g[base]; swr[m] = d_wr_g[base]; scls[m] = d_cls_g[base];
    }
    __syncthreads();
    if (m < 32) {
        int nn = 0;
#pragma unroll
        for (int chunk = 0; chunk < 4; chunk++) {
            int j = chunk*32 + lane;
            bool p = sgy[j] > 0.0f;
            unsigned mb = __ballot_sync(0xffffffffu, p);
            int pos = nn + __popc(mb & ((1u << lane) - 1u));
            if (p) slist[pos] = (short)j;
            nn += __popc(mb);
        }
        if (lane == 0) s_n = nn;
    }
    __syncthreads();
    int n = s_n;

    unsigned covm[4] = {0u,0u,0u,0u};
    int e_w = -1;
    for (int e = 0; e < n; e++) {
        int j = slist[e];
        int dx = x - scx[j];
        if (abs(dx) <= swr[j]) {
            covm[e >> 5] |= 1u << (e & 31);
            e_w = e;
        }
    }

    float lsum = 0.0f;
    int   lnp  = 0;
    const float* hmr = hm + (((size_t)b*NUMC)*OH + y)*OW + x;

    for (int e = 0; e < n; e++) {
        if (!((covm[e >> 5] >> (e & 31)) & 1u)) continue;
        int j = slist[e];
        int c = scls[j];
        float dxf = (float)(x - scx[j]);
        float g = sgy[j] * __expf(-dxf*dxf * si2sx[j]);
        bool rep = true;
        for (int e2 = 0; e2 < n; e2++) {
            if (e2 == e) continue;
            if (!((covm[e2 >> 5] >> (e2 & 31)) & 1u)) continue;
            int j2 = slist[e2];
            if (scls[j2] != c) continue;
            float dx2 = (float)(x - scx[j2]);
            float g2 = sgy[j2] * __expf(-dx2*dx2 * si2sx[j2]);
            if (g2 > g || (g2 == g && e2 < e)) { rep = false; break; }
        }
        if (!rep) continue;
        float xv = hmr[(size_t)c * PLANE];
        float p;
        float u = focal_neg_base(xv, p);
        if (g == 1.0f) {
            float omp = 1.0f - p;
            float vv = __logf(p) * omp * omp;
            lsum += vv - u;
            lnp++;
        } else {
            float omh = 1.0f - g;
            float w4 = omh * omh; w4 *= w4;
            lsum += u * (w4 - 1.0f);
        }
    }

    float lwhn = 0.0f, lrw = 0.0f;
    if (e_w >= 0) {
        int j = slist[e_w];
        float dxf = (float)(x - scx[j]);
        float g = sgy[j] * __expf(-dxf*dxf * si2sx[j]);
        float rw = g * scoef[j];
        size_t pbase = (((size_t)b*4)*OH + y)*OW + x;
        float pl = wh[pbase            ] * 16.0f;
        float pt = wh[pbase +   PLANE  ] * 16.0f;
        float pr = wh[pbase + 2*PLANE  ] * 16.0f;
        float pb = wh[pbase + 3*PLANE  ] * 16.0f;
        float xs = (float)x * 4.0f, ys = (float)y * 4.0f;
        float tl = xs - sx1[j];
        float tt = ys - sy1s[j];
        float tr = sx2[j] - xs;
        float tb = sy2s[j] - ys;
        float ta = (tl + tr) * (tt + tb);
        float pa = (pl + pr) * (pt + pb);
        float wi = fminf(pl, tl) + fminf(pr, tr);
        float hi = fminf(pt, tt) + fminf(pb, tb);
        float ai = wi * hi;
        float au = ta + pa - ai;
        float iou = (ai + 1.0f) / (au + 1.0f);
        lwhn = (rw > 0.0f) ? (1.0f - iou) * rw : 0.0f;
        lrw = rw;
    }

    // ---- block reduce -> double atomics (R4 shape) ----
    for (int off = 16; off; off >>= 1) {
        lsum += __shfl_down_sync(0xffffffffu, lsum, off);
        lwhn += __shfl_down_sync(0xffffffffu, lwhn, off);
        lrw  += __shfl_down_sync(0xffffffffu, lrw,  off);
        lnp  += __shfl_down_sync(0xffffffffu, lnp,  off);
    }
    __shared__ float r0[4], r1[4], r2[4];
    __shared__ int   r3[4];
    int wid = m >> 5;
    if (lane == 0) { r0[wid]=lsum; r1[wid]=lwhn; r2[wid]=lrw; r3[wid]=lnp; }
    __syncthreads();
    if (m == 0) {
        float a=0.f, c1=0.f, c2=0.f; int np=0;
        for (int i = 0; i < 4; i++) { a+=r0[i]; c1+=r1[i]; c2+=r2[i]; np+=r3[i]; }
        atomicAdd(&d_acc_hm,  (double)a);
        atomicAdd(&d_acc_whn, (double)c1);
        atomicAdd(&d_acc_rw,  (double)c2);
        atomicAdd(&d_acc_np,  np);
    }

    // ---- ticket: last sparse block finalizes + resets ----
    __shared__ bool amLast;
    __threadfence();
    __syncthreads();
    if (m == 0)
        amLast = (atomicAdd(&d_spa_ctr, 1u) == (unsigned)(NSPA - 1));
    __syncthreads();
    if (amLast && m == 0) {
        double thm = *((volatile double*)&d_acc_hm);
        double twn = *((volatile double*)&d_acc_whn);
        double trw = *((volatile double*)&d_acc_rw);
        int    tnp = *((volatile int*)&d_acc_np);
        double hml = (tnp > 0) ? (-thm / (double)(tnp < 1 ? 1 : tnp)) : -thm;
        double whl = twn / fmax(trw, 1.0);
        out[0] = (float)(hml + whl);
        d_acc_hm = 0.0; d_acc_whn = 0.0; d_acc_rw = 0.0; d_acc_np = 0;
        d_spa_ctr = 0u;
    }
}

extern "C" void kernel_launch(void* const* d_in, const int* in_sizes, int n_in,
                              void* d_out, int out_size) {
    const float* hm   = (const float*)d_in[0];
    const float* wh   = (const float*)d_in[1];
    const float* tgt  = (const float*)d_in[2];
    const void*  mask = (const void*)d_in[3];
    float* out = (float*)d_out;
    (void)in_sizes; (void)n_in; (void)out_size;

    base_kernel<<<NBASE, 256>>>((const float4*)hm, tgt, mask);
    sparse_kernel<<<dim3(OH, BATCH), 128>>>(hm, wh, out);
}

// round 17
// speedup vs baseline: 1.6618x; 1.0440x over previous
#include <cuda_runtime.h>
#include <math.h>
#include <stdint.h>

#define BATCH 16
#define KBOX  128
#define NUMC  80
#define OH    128
#define OW    128
#define NB    (BATCH*KBOX)
#define PLANE (OH*OW)
#define NBASE 2560                 // (16*80*128*128/4) / (256*8)
#define NSPA  (OH*BATCH)           // 2048

// ---- packed per-box state (sorted order), written by base prep branch ----
__device__ float4 d_boxA[NB];   // x1, y1, x2, y2
__device__ float4 d_boxB[NB];   // i2sy, i2sx, coef, cls(float)
__device__ int4   d_boxC[NB];   // cx, cy, hr(-1 if inactive), wr

// ---- global accumulators + sparse ticket (self-resetting) ----
__device__ double d_acc_hm;
__device__ double d_acc_whn;
__device__ double d_acc_rw;
__device__ int    d_acc_np;
__device__ unsigned int d_spa_ctr;

// u(x) = log(1 - clip(sigmoid(x))) * clip(sigmoid(x))^2   (3 MUFU)
__device__ __forceinline__ float focal_neg_base(float xv, float& p_out) {
    float t = __expf(-xv);
    float p = __fdividef(1.0f, 1.0f + t);
    p = fminf(fmaxf(p, 1e-4f), 0.9999f);
    p_out = p;
    float omp = 1.0f - p;
    return __logf(omp) * p * p;
}

// =====================================================================
// base: blocks 0..15 run prep for image bid first (once each), then all
// 2560 blocks stream 2048 float4 of the focal base term.
// =====================================================================
__global__ void __launch_bounds__(256)
base_kernel(const float4* __restrict__ hm4,
            const float* __restrict__ tgt,
            const void*  __restrict__ mraw) {
    int bid = blockIdx.x;
    int tid = threadIdx.x;

    if (bid < BATCH) {
        // -------- prep for image b = bid (256 threads, split y/x sums) ----
        int b = bid;
        int k2 = tid & 127;
        __shared__ int   s_gt1, s_off4;
        __shared__ int   smask[KBOX];
        __shared__ float skey[KBOX];
        __shared__ int   sperm[KBOX];
        __shared__ float s_al0;
        __shared__ float sdy[KBOX], sdx[KBOX];

        if (tid == 0) { s_gt1 = 0; s_off4 = 0; }
        __syncthreads();
        {
            const uint8_t* b8 = (const uint8_t*)mraw;
            int gt1 = 0, off4 = 0;
#pragma unroll
            for (int c = 0; c < NB/256; c++) {
                int i = c*256 + tid;
                uint8_t vv = b8[i];
                gt1  |= (vv > 1);
                off4 |= (vv != 0) && ((i & 3) != 0);
            }
            if (gt1)  atomicOr(&s_gt1, 1);
            if (off4) atomicOr(&s_off4, 1);
        }
        __syncthreads();
        int u8mode = (!s_gt1) && s_off4;
        if (tid < KBOX) {
            int i = b*KBOX + tid;
            smask[tid] = u8mode ? (((const uint8_t*)mraw)[i] != 0)
                                : (((const uint32_t*)mraw)[i] != 0u);
        }
        __syncthreads();
        if (tid < KBOX) {
            const float* t = tgt + (size_t)(b*KBOX + tid)*5;
            float x1 = t[1], y1 = t[2], x2 = t[3], y2 = t[4];
            float area = (x2 - x1) * (y2 - y1);
            skey[tid] = smask[tid] ? __logf(area) : -INFINITY;
        }
        __syncthreads();
        if (tid < KBOX) {
            float key = skey[tid];
            int rank = 0;
#pragma unroll 16
            for (int j = 0; j < KBOX; j++) {
                float kj = skey[j];
                rank += (kj > key) || (kj == key && j < tid);
            }
            sperm[rank] = tid;
        }
        __syncthreads();
        if (tid == 0) {
            int o0 = sperm[0];
            s_al0 = smask[o0] ? skey[o0] : 0.0f;
        }
        __syncthreads();
        {
            int o = sperm[k2];
            const float* to = tgt + (size_t)(b*KBOX + o)*5;
            float clsf = to[0];
            float ox1 = to[1], oy1 = to[2], ox2 = to[3], oy2 = to[4];
            int v = smask[o];
            float keyo = skey[o];

            float fx1 = fminf(fmaxf(ox1 * 0.25f, 0.0f), (float)(OW-1));
            float fy1 = fminf(fmaxf(oy1 * 0.25f, 0.0f), (float)(OH-1));
            float fx2 = fminf(fmaxf(ox2 * 0.25f, 0.0f), (float)(OW-1));
            float fy2 = fminf(fmaxf(oy2 * 0.25f, 0.0f), (float)(OH-1));
            float feat_h = fy2 - fy1;
            float feat_w = fx2 - fx1;

            int cx = (int)(((ox1 + ox2) * 0.5f) * 0.25f);
            int cy = (int)(((oy1 + oy2) * 0.5f) * 0.25f);
            int hr = (int)((feat_h * 0.5f) * 0.54f);
            int wr = (int)((feat_w * 0.5f) * 0.54f);
            float sy = (float)(2*hr + 1) / 6.0f;
            float sx = (float)(2*wr + 1) / 6.0f;
            float i2sy = 1.0f / (2.0f * sy * sy);
            float i2sx = 1.0f / (2.0f * sx * sx);

            int act = v && (cx >= 0) && (cx < OW) && (cy >= 0) && (cy < OH);

            if (tid < KBOX) {
                float sgy = 0.0f;
                if (act) {
                    int ya = max(0, cy - hr), yb = min(OH-1, cy + hr);
                    for (int yy = ya; yy <= yb; yy++) {
                        float d = (float)(yy - cy);
                        sgy += __expf(-(d*d) * i2sy);
                    }
                }
                sdy[k2] = sgy;
            } else {
                float sgx = 0.0f;
                if (act) {
                    int xa = max(0, cx - wr), xb = min(OW-1, cx + wr);
                    for (int xx = xa; xx <= xb; xx++) {
                        float d = (float)(xx - cx);
                        sgx += __expf(-(d*d) * i2sx);
                    }
                }
                sdx[k2] = sgx;
            }
            __syncthreads();
            if (tid < KBOX) {
                float divs = act ? (sdy[k2] * sdx[k2]) : 0.0f;
                float al = v ? keyo : 0.0f;
                float factor = 2.0f - al / (s_al0 + 1e-7f);
                float coef = act ? (factor / (divs + 1e-7f)) : 0.0f;

                int idx = b*KBOX + k2;
                d_boxA[idx] = make_float4(ox1, oy1, ox2, oy2);
                d_boxB[idx] = make_float4(i2sy, i2sx, coef, clsf);
                d_boxC[idx] = make_int4(cx, cy, act ? hr : -1, wr);
            }
        }
        __syncthreads();
    }

    // -------- streaming focal base term (all blocks) --------
    int idx = bid * (256*8) + tid;
    float4 v[8];
#pragma unroll
    for (int u = 0; u < 8; u++) v[u] = __ldg(&hm4[idx + u*256]);
    float lsum = 0.0f;
#pragma unroll
    for (int u = 0; u < 8; u++) {
        float p;
        lsum += focal_neg_base(v[u].x, p);
        lsum += focal_neg_base(v[u].y, p);
        lsum += focal_neg_base(v[u].z, p);
        lsum += focal_neg_base(v[u].w, p);
    }

    for (int off = 16; off; off >>= 1)
        lsum += __shfl_down_sync(0xffffffffu, lsum, off);
    __shared__ float r[8];
    int w = tid >> 5;
    if ((tid & 31) == 0) r[w] = lsum;
    __syncthreads();
    if (tid == 0) {
        float a = 0.0f;
#pragma unroll
        for (int i = 0; i < 8; i++) a += r[i];
        atomicAdd(&d_acc_hm, (double)a);
    }
}

// =====================================================================
// sparse: grid=(OH, BATCH), 128 threads, 1 row/block (R4-proven shape).
// 3 vector loads per thread for box state. Last block finalizes.
// =====================================================================
__global__ void __launch_bounds__(128)
sparse_kernel(const float* __restrict__ hm,
              const float* __restrict__ wh,
              float* __restrict__ out) {
    int y = blockIdx.x, b = blockIdx.y, x = threadIdx.x;
    int m = threadIdx.x;
    int lane = m & 31;

    __shared__ float sgy[KBOX];
    __shared__ float sx1[KBOX], sy1s[KBOX], sx2[KBOX], sy2s[KBOX];
    __shared__ float scoef[KBOX], si2sx[KBOX];
    __shared__ int   scx[KBOX], swr[KBOX], scls[KBOX];
    __shared__ short slist[KBOX];
    __shared__ int   s_n;

    {
        int base = b*KBOX + m;
        float4 bA = d_boxA[base];
        float4 bB = d_boxB[base];
        int4   bC = d_boxC[base];
        int dy = y - bC.y;
        int rowcov = (abs(dy) <= bC.z);          // hr=-1 if inactive
        sgy[m] = rowcov ? __expf(-(float)(dy*dy) * bB.x) : 0.0f;
        sx1[m] = bA.x; sy1s[m] = bA.y; sx2[m] = bA.z; sy2s[m] = bA.w;
        scoef[m] = bB.z; si2sx[m] = bB.y;
        scx[m] = bC.x; swr[m] = bC.w; scls[m] = (int)bB.w;
    }
    __syncthreads();
    if (m < 32) {
        int nn = 0;
#pragma unroll
        for (int chunk = 0; chunk < 4; chunk++) {
            int j = chunk*32 + lane;
            bool p = sgy[j] > 0.0f;
            unsigned mb = __ballot_sync(0xffffffffu, p);
            int pos = nn + __popc(mb & ((1u << lane) - 1u));
            if (p) slist[pos] = (short)j;
            nn += __popc(mb);
        }
        if (lane == 0) s_n = nn;
    }
    __syncthreads();
    int n = s_n;

    unsigned covm[4] = {0u,0u,0u,0u};
    int e_w = -1;
    for (int e = 0; e < n; e++) {
        int j = slist[e];
        int dx = x - scx[j];
        if (abs(dx) <= swr[j]) {
            covm[e >> 5] |= 1u << (e & 31);
            e_w = e;
        }
    }

    float lsum = 0.0f;
    int   lnp  = 0;
    const float* hmr = hm + (((size_t)b*NUMC)*OH + y)*OW + x;

    for (int e = 0; e < n; e++) {
        if (!((covm[e >> 5] >> (e & 31)) & 1u)) continue;
        int j = slist[e];
        int c = scls[j];
        float dxf = (float)(x - scx[j]);
        float g = sgy[j] * __expf(-dxf*dxf * si2sx[j]);
        bool rep = true;
        for (int e2 = 0; e2 < n; e2++) {
            if (e2 == e) continue;
            if (!((covm[e2 >> 5] >> (e2 & 31)) & 1u)) continue;
            int j2 = slist[e2];
            if (scls[j2] != c) continue;
            float dx2 = (float)(x - scx[j2]);
            float g2 = sgy[j2] * __expf(-dx2*dx2 * si2sx[j2]);
            if (g2 > g || (g2 == g && e2 < e)) { rep = false; break; }
        }
        if (!rep) continue;
        float xv = hmr[(size_t)c * PLANE];
        float p;
        float u = focal_neg_base(xv, p);
        if (g == 1.0f) {
            float omp = 1.0f - p;
            float vv = __logf(p) * omp * omp;
            lsum += vv - u;
            lnp++;
        } else {
            float omh = 1.0f - g;
            float w4 = omh * omh; w4 *= w4;
            lsum += u * (w4 - 1.0f);
        }
    }

    float lwhn = 0.0f, lrw = 0.0f;
    if (e_w >= 0) {
        int j = slist[e_w];
        float dxf = (float)(x - scx[j]);
        float g = sgy[j] * __expf(-dxf*dxf * si2sx[j]);
        float rw = g * scoef[j];
        size_t pbase = (((size_t)b*4)*OH + y)*OW + x;
        float pl = wh[pbase            ] * 16.0f;
        float pt = wh[pbase +   PLANE  ] * 16.0f;
        float pr = wh[pbase + 2*PLANE  ] * 16.0f;
        float pb = wh[pbase + 3*PLANE  ] * 16.0f;
        float xs = (float)x * 4.0f, ys = (float)y * 4.0f;
        float tl = xs - sx1[j];
        float tt = ys - sy1s[j];
        float tr = sx2[j] - xs;
        float tb = sy2s[j] - ys;
        float ta = (tl + tr) * (tt + tb);
        float pa = (pl + pr) * (pt + pb);
        float wi = fminf(pl, tl) + fminf(pr, tr);
        float hi = fminf(pt, tt) + fminf(pb, tb);
        float ai = wi * hi;
        float au = ta + pa - ai;
        float iou = (ai + 1.0f) / (au + 1.0f);
        lwhn = (rw > 0.0f) ? (1.0f - iou) * rw : 0.0f;
        lrw = rw;
    }

    // ---- block reduce -> double atomics ----
    for (int off = 16; off; off >>= 1) {
        lsum += __shfl_down_sync(0xffffffffu, lsum, off);
        lwhn += __shfl_down_sync(0xffffffffu, lwhn, off);
        lrw  += __shfl_down_sync(0xffffffffu, lrw,  off);
        lnp  += __shfl_down_sync(0xffffffffu, lnp,  off);
    }
    __shared__ float r0[4], r1[4], r2[4];
    __shared__ int   r3[4];
    int wid = m >> 5;
    if (lane == 0) { r0[wid]=lsum; r1[wid]=lwhn; r2[wid]=lrw; r3[wid]=lnp; }
    __syncthreads();
    if (m == 0) {
        float a=0.f, c1=0.f, c2=0.f; int np=0;
        for (int i = 0; i < 4; i++) { a+=r0[i]; c1+=r1[i]; c2+=r2[i]; np+=r3[i]; }
        atomicAdd(&d_acc_hm,  (double)a);
        atomicAdd(&d_acc_whn, (double)c1);
        atomicAdd(&d_acc_rw,  (double)c2);
        atomicAdd(&d_acc_np,  np);
    }

    // ---- ticket: last sparse block finalizes + resets ----
    __shared__ bool amLast;
    __threadfence();
    __syncthreads();
    if (m == 0)
        amLast = (atomicAdd(&d_spa_ctr, 1u) == (unsigned)(NSPA - 1));
    __syncthreads();
    if (amLast && m == 0) {
        double thm = *((volatile double*)&d_acc_hm);
        double twn = *((volatile double*)&d_acc_whn);
        double trw = *((volatile double*)&d_acc_rw);
        int    tnp = *((volatile int*)&d_acc_np);
        double hml = (tnp > 0) ? (-thm / (double)(tnp < 1 ? 1 : tnp)) : -thm;
        double whl = twn / fmax(trw, 1.0);
        out[0] = (float)(hml + whl);
        d_acc_hm = 0.0; d_acc_whn = 0.0; d_acc_rw = 0.0; d_acc_np = 0;
        d_spa_ctr = 0u;
    }
}

extern "C" void kernel_launch(void* const* d_in, const int* in_sizes, int n_in,
                              void* d_out, int out_size) {
    const float* hm   = (const float*)d_in[0];
    const float* wh   = (const float*)d_in[1];
    const float* tgt  = (const float*)d_in[2];
    const void*  mask = (const void*)d_in[3];
    float* out = (float*)d_out;
    (void)in_sizes; (void)n_in; (void)out_size;

    base_kernel<<<NBASE, 256>>>((const float4*)hm, tgt, mask);
    sparse_kernel<<<dim3(OH, BATCH), 128>>>(hm, wh, out);
}